// round 14
// baseline (speedup 1.0000x reference)
#include <cuda_runtime.h>
#include <cuda_bf16.h>
#include <math.h>
#include <stdint.h>

#define BB 4
#define SS 2048
#define HH 16
#define DD 128
#define DH 64    // effective qk dim (first half, duplicated in reference)
#define BM 128
#define BN 64
#define NTHR 384

typedef unsigned long long u64;

// ---- scratch (no allocs allowed) ----
__device__ float g_Qp[BB*HH*DH*SS];                  // [b,h,kdim,s]  33.5 MB
__device__ float g_Kp[BB*HH*DH*SS];                  // [b,h,kdim,s]  33.5 MB
__device__ __nv_bfloat16 g_Vhi[(size_t)BB*HH*SS*DD]; // [b,h,s,d]     33.5 MB
__device__ __nv_bfloat16 g_Vlo[(size_t)BB*HH*SS*DD]; // [b,h,s,d]     33.5 MB
__device__ float g_inv[DH];

// ---- smem layout (bytes) ----
#define OFF_QST 0            // fp32 Q [64 kdim][128 m]          32768
#define OFF_KS  32768        // fp32 K 2 x [64 kdim][64 n]       32768
#define OFF_VHI 65536        // bf16 Vhi 2 x [64 k][128 d]       34816 (row 272B)
#define OFF_VLO 100352       // bf16 Vlo 2 x                     34816
#define OFF_PHI 135168       // bf16 P  2 x (hi 18432 + lo 18432) = 73728
#define OFF_F   208896       // float f 2 x 128
#define OFF_L   209920       // float l[128]
#define SMEM_TOTAL 210432
#define VROWB 272            // ≡ 4 words mod 32 banks -> conflict-free ldmatrix
#define VTILE 17408          // 64 * 272 (per split per buffer)
#define VLO_DELTA 34816      // OFF_VLO - OFF_VHI
#define PROWB 144            // ≡ 4 words mod 32
#define PBUF 36864           // per P buffer (hi+lo)
#define PLO_DELTA 18432

// ---------------- packed f32x2 helpers (GEMM1) ----------------
__device__ __forceinline__ u64 bcast2(float x) {
    u64 r; asm("mov.b64 %0, {%1, %1};" : "=l"(r) : "f"(x)); return r;
}
__device__ __forceinline__ void ffma2(u64& d, u64 a, u64 b) {
    asm("fma.rn.f32x2 %0, %1, %2, %3;" : "=l"(d) : "l"(a), "l"(b), "l"(d));
}
__device__ __forceinline__ void unpack2(u64 v, float& lo, float& hi) {
    asm("mov.b64 {%0, %1}, %2;" : "=f"(lo), "=f"(hi) : "l"(v));
}

// ---------------- cp.async ----------------
__device__ __forceinline__ void cp_async16(uint32_t saddr, const void* gptr) {
    asm volatile("cp.async.cg.shared.global [%0], [%1], 16;" :: "r"(saddr), "l"(gptr));
}
__device__ __forceinline__ void cp_commit() { asm volatile("cp.async.commit_group;"); }
__device__ __forceinline__ void cp_wait_all() { asm volatile("cp.async.wait_group 0;"); }
__device__ __forceinline__ void cp_wait_1()  { asm volatile("cp.async.wait_group 1;"); }

// ---------------- tensor core: ldmatrix + mma.sync (base PTX) ----------------
__device__ __forceinline__ void ldmx4(uint32_t* r, uint32_t a) {
    asm volatile("ldmatrix.sync.aligned.m8n8.x4.shared.b16 {%0,%1,%2,%3}, [%4];"
        : "=r"(r[0]), "=r"(r[1]), "=r"(r[2]), "=r"(r[3]) : "r"(a));
}
__device__ __forceinline__ void ldmx4t(uint32_t* r, uint32_t a) {
    asm volatile("ldmatrix.sync.aligned.m8n8.x4.trans.shared.b16 {%0,%1,%2,%3}, [%4];"
        : "=r"(r[0]), "=r"(r[1]), "=r"(r[2]), "=r"(r[3]) : "r"(a));
}
__device__ __forceinline__ void mma16816(float* c, const uint32_t* a, const uint32_t* b) {
    asm volatile("mma.sync.aligned.m16n8k16.row.col.f32.bf16.bf16.f32 "
        "{%0,%1,%2,%3}, {%4,%5,%6,%7}, {%8,%9}, {%0,%1,%2,%3};"
        : "+f"(c[0]), "+f"(c[1]), "+f"(c[2]), "+f"(c[3])
        : "r"(a[0]), "r"(a[1]), "r"(a[2]), "r"(a[3]), "r"(b[0]), "r"(b[1]));
}

// ---------------- prep ----------------
__global__ void init_inv() {
    int i = threadIdx.x;
    g_inv[i] = (float)exp(-(double)i * (9.210340371976184 / 64.0)); // ln(1e4)/64
}

__global__ void prep_qk(const float* __restrict__ q, const float* __restrict__ k) {
    __shared__ float qs[64*65];
    __shared__ float ks[64*65];
    const int st = blockIdx.x, h = blockIdx.y, b = blockIdx.z;
    const int tid = threadIdx.x;
    for (int idx = tid; idx < 64*64; idx += 256) {
        int sl = idx >> 6, i = idx & 63;
        int s = st*64 + sl;
        float fc = 2.0f * ((float)s * g_inv[i]);
        size_t gin = ((size_t)(b*SS + s)*HH + h)*DD + i;
        qs[i*65 + sl] = q[gin] * fc;
        ks[i*65 + sl] = k[gin] * fc;
    }
    __syncthreads();
    float* Qo = g_Qp + (size_t)((b*HH + h)*DH)*SS + st*64;
    float* Ko = g_Kp + (size_t)((b*HH + h)*DH)*SS + st*64;
    for (int idx = tid; idx < 64*64; idx += 256) {
        int i = idx >> 6, sl = idx & 63;
        Qo[(size_t)i*SS + sl] = qs[i*65 + sl];
        Ko[(size_t)i*SS + sl] = ks[i*65 + sl];
    }
}

__global__ void prep_v(const float* __restrict__ v) {
    const int st = blockIdx.x, h = blockIdx.y, b = blockIdx.z;
    const int tid = threadIdx.x;
    for (int idx = tid; idx < 64*32; idx += 256) {
        int s = idx >> 5, d4 = idx & 31;
        float4 x = *(const float4*)&v[((size_t)(b*SS + st*64 + s)*HH + h)*DD + d4*4];
        __nv_bfloat16 h0 = __float2bfloat16(x.x), h1 = __float2bfloat16(x.y);
        __nv_bfloat16 h2 = __float2bfloat16(x.z), h3 = __float2bfloat16(x.w);
        __nv_bfloat16 l0 = __float2bfloat16(x.x - __bfloat162float(h0));
        __nv_bfloat16 l1 = __float2bfloat16(x.y - __bfloat162float(h1));
        __nv_bfloat16 l2 = __float2bfloat16(x.z - __bfloat162float(h2));
        __nv_bfloat16 l3 = __float2bfloat16(x.w - __bfloat162float(h3));
        size_t o = ((size_t)(b*HH + h)*SS + st*64 + s)*DD + d4*4;
        __nv_bfloat162* ph = (__nv_bfloat162*)(g_Vhi + o);
        __nv_bfloat162* pl = (__nv_bfloat162*)(g_Vlo + o);
        __nv_bfloat162 a; a.x = h0; a.y = h1; ph[0] = a;
        a.x = h2; a.y = h3; ph[1] = a;
        a.x = l0; a.y = l1; pl[0] = a;
        a.x = l2; a.y = l3; pl[1] = a;
    }
}

// ---------------- attn building blocks ----------------
__device__ __forceinline__ void gemm1_chunk(const float* QsT, const float* KsT,
                                            int ti, int tj, int ks, u64 acc2[4][4]) {
    #pragma unroll
    for (int i = 0; i < 16; i++) {
        int kk = ks*16 + i;
        ulonglong2 a01 = *(const ulonglong2*)&QsT[(kk << 7) + (ti << 3)];
        ulonglong2 a23 = *(const ulonglong2*)&QsT[(kk << 7) + (ti << 3) + 4];
        float4 b4 = *(const float4*)&KsT[(kk << 6) + (tj << 2)];
        u64 b0 = bcast2(b4.x), b1 = bcast2(b4.y);
        u64 b2 = bcast2(b4.z), b3 = bcast2(b4.w);
        ffma2(acc2[0][0], a01.x, b0); ffma2(acc2[0][1], a01.x, b1);
        ffma2(acc2[0][2], a01.x, b2); ffma2(acc2[0][3], a01.x, b3);
        ffma2(acc2[1][0], a01.y, b0); ffma2(acc2[1][1], a01.y, b1);
        ffma2(acc2[1][2], a01.y, b2); ffma2(acc2[1][3], a01.y, b3);
        ffma2(acc2[2][0], a23.x, b0); ffma2(acc2[2][1], a23.x, b1);
        ffma2(acc2[2][2], a23.x, b2); ffma2(acc2[2][3], a23.x, b3);
        ffma2(acc2[3][0], a23.y, b0); ffma2(acc2[3][1], a23.y, b1);
        ffma2(acc2[3][2], a23.y, b2); ffma2(acc2[3][3], a23.y, b3);
    }
}

// GEMM2 chunk for one ks: warp covers 32 rows x FULL 128 d.
// P fragments loaded once, reused for both 64-d halves (c = c[2][64] flattened).
__device__ __forceinline__ void gemm2_chunk2(uint32_t pa, uint32_t vb, int ks, float* cc) {
    uint32_t ko = (uint32_t)(ks*16)*VROWB;
    uint32_t ahi0[4], alo0[4], ahi1[4], alo1[4];
    ldmx4(ahi0, pa + ks*32);
    ldmx4(alo0, pa + PLO_DELTA + ks*32);
    ldmx4(ahi1, pa + 16*PROWB + ks*32);
    ldmx4(alo1, pa + PLO_DELTA + 16*PROWB + ks*32);
    #pragma unroll
    for (int dh = 0; dh < 2; dh++) {
        float* c = cc + dh*64;
        uint32_t vbd = vb + (uint32_t)dh*128;
        #pragma unroll
        for (int nb = 0; nb < 4; nb++) {
            uint32_t bh[4], bl[4];
            ldmx4t(bh, vbd + ko + nb*32);
            ldmx4t(bl, vbd + VLO_DELTA + ko + nb*32);
            mma16816(&c[(2*nb)*4],          ahi0, bh);
            mma16816(&c[(2*nb)*4],          ahi0, bl);
            mma16816(&c[(2*nb)*4],          alo0, bh);
            mma16816(&c[(2*nb + 1)*4],      ahi0, bh + 2);
            mma16816(&c[(2*nb + 1)*4],      ahi0, bl + 2);
            mma16816(&c[(2*nb + 1)*4],      alo0, bh + 2);
            mma16816(&c[(8 + 2*nb)*4],      ahi1, bh);
            mma16816(&c[(8 + 2*nb)*4],      ahi1, bl);
            mma16816(&c[(8 + 2*nb)*4],      alo1, bh);
            mma16816(&c[(8 + 2*nb + 1)*4],  ahi1, bh + 2);
            mma16816(&c[(8 + 2*nb + 1)*4],  ahi1, bl + 2);
            mma16816(&c[(8 + 2*nb + 1)*4],  alo1, bh + 2);
        }
    }
}

__device__ __forceinline__ void rescale_c2(float* cc, const float* fprev, int rg, int lane) {
    #pragma unroll
    for (int mt = 0; mt < 2; mt++) {
        float f0 = fprev[rg*32 + mt*16 + (lane >> 2)];
        float f1 = fprev[rg*32 + mt*16 + (lane >> 2) + 8];
        #pragma unroll
        for (int dh = 0; dh < 2; dh++)
            #pragma unroll
            for (int nt = 0; nt < 8; nt++) {
                cc[dh*64 + (mt*8 + nt)*4 + 0] *= f0;
                cc[dh*64 + (mt*8 + nt)*4 + 1] *= f0;
                cc[dh*64 + (mt*8 + nt)*4 + 2] *= f1;
                cc[dh*64 + (mt*8 + nt)*4 + 3] *= f1;
            }
    }
}

__device__ __forceinline__ void softmax_tile(u64 acc2[4][4], float* mrow, float* lrow,
                                             char* smem, uint32_t phi_off, float* fptr,
                                             int ti, int tj) {
    float p[8][4];
    #pragma unroll
    for (int mp = 0; mp < 4; mp++)
        #pragma unroll
        for (int n = 0; n < 4; n++)
            unpack2(acc2[mp][n], p[2*mp][n], p[2*mp + 1][n]);

    const float sc2 = 1.44269504088896340736f / 64.0f;  // log2(e)/64

    float mx[8];
    #pragma unroll
    for (int r = 0; r < 8; r++)
        mx[r] = fmaxf(fmaxf(p[r][0], p[r][1]), fmaxf(p[r][2], p[r][3]));
    #pragma unroll
    for (int st = 1; st < 16; st <<= 1)
        #pragma unroll
        for (int r = 0; r < 8; r++)
            mx[r] = fmaxf(mx[r], __shfl_xor_sync(0xffffffffu, mx[r], st));

    float fr[8];
    #pragma unroll
    for (int r = 0; r < 8; r++) {
        float mn = fmaxf(mrow[r], mx[r]*sc2);
        fr[r] = exp2f(mrow[r] - mn);   // 0 on first tile
        mrow[r] = mn;
    }

    float sr[8];
    #pragma unroll
    for (int r = 0; r < 8; r++) {
        #pragma unroll
        for (int cx = 0; cx < 4; cx++)
            p[r][cx] = exp2f(fmaf(p[r][cx], sc2, -mrow[r]));
        sr[r] = (p[r][0] + p[r][1]) + (p[r][2] + p[r][3]);

        int rr = ti*8 + r;
        __nv_bfloat16 h0 = __float2bfloat16(p[r][0]), h1 = __float2bfloat16(p[r][1]);
        __nv_bfloat16 h2 = __float2bfloat16(p[r][2]), h3 = __float2bfloat16(p[r][3]);
        __nv_bfloat162 hh01; hh01.x = h0; hh01.y = h1;
        __nv_bfloat162 hh23; hh23.x = h2; hh23.y = h3;
        __nv_bfloat162 ll01, ll23;
        ll01.x = __float2bfloat16(p[r][0] - __bfloat162float(h0));
        ll01.y = __float2bfloat16(p[r][1] - __bfloat162float(h1));
        ll23.x = __float2bfloat16(p[r][2] - __bfloat162float(h2));
        ll23.y = __float2bfloat16(p[r][3] - __bfloat162float(h3));
        *(uint2*)(smem + phi_off + rr*PROWB + tj*8) =
            make_uint2(*(uint32_t*)&hh01, *(uint32_t*)&hh23);
        *(uint2*)(smem + phi_off + PLO_DELTA + rr*PROWB + tj*8) =
            make_uint2(*(uint32_t*)&ll01, *(uint32_t*)&ll23);
        if (tj == 0) fptr[rr] = fr[r];
    }
    #pragma unroll
    for (int st = 1; st < 16; st <<= 1)
        #pragma unroll
        for (int r = 0; r < 8; r++)
            sr[r] += __shfl_xor_sync(0xffffffffu, sr[r], st);
    #pragma unroll
    for (int r = 0; r < 8; r++)
        lrow[r] = lrow[r]*fr[r] + sr[r];
}

// ---------------- warp-specialized flash attention (384 threads) ----------------
// 12 warps. WG-A (warps 0-7, 256 thr): GEMM1 + softmax -> P/f.
// WG-B (warps 8-11, 128 thr): HMMA GEMM2 one tile behind; warp rg owns
// rows rg*32..+31 x full 128 d (P frags loaded once, reused for both d-halves).
// Per SMSP: 2 A-warps + 1 B-warp. Reg budget 65536/384 = 170.
__global__ __launch_bounds__(NTHR, 1)
void attn_kernel(float* __restrict__ out) {
    extern __shared__ char smem[];
    const uint32_t sbase = (uint32_t)__cvta_generic_to_shared(smem);
    float* QsT = (float*)(smem + OFF_QST);
    float* lptr = (float*)(smem + OFF_L);

    const int qt = blockIdx.x, h = blockIdx.y, b = blockIdx.z;
    const int tid = threadIdx.x;
    const int wid = tid >> 5, lane = tid & 31;
    const bool isA = (wid < 8);
    const int ti = (tid & 255) >> 4, tj = tid & 15;   // WG-A layout
    const int rg = wid - 8;                            // WG-B warp 0..3 -> rows rg*32..+31

    const float* Qg  = g_Qp + (size_t)((b*HH + h)*DH)*SS + qt*BM;
    const float* Kg0 = g_Kp + (size_t)((b*HH + h)*DH)*SS;
    const __nv_bfloat16* Vh0 = g_Vhi + (size_t)(b*HH + h)*SS*DD;
    const __nv_bfloat16* Vl0 = g_Vlo + (size_t)(b*HH + h)*SS*DD;

    // warp-fixed GEMM2 base addresses (WG-B only; harmless for A)
    const uint32_t pa_base = sbase + OFF_PHI + (uint32_t)(rg*32 + (lane & 15))*PROWB
                           + ((lane >> 4) << 4);
    const uint32_t vb_base = sbase + OFF_VHI + (uint32_t)(lane & 15)*VROWB
                           + ((lane >> 4) << 4);

    // ---- prologue: Q + K0 + V0 (all 384 threads) ----
    for (int idx4 = tid; idx4 < 2048; idx4 += NTHR) {
        int kk = idx4 >> 5, m4 = idx4 & 31;
        cp_async16(sbase + OFF_QST + (uint32_t)idx4*16, Qg + (size_t)kk*SS + m4*4);
    }
    for (int idx4 = tid; idx4 < 1024; idx4 += NTHR) {   // K tile = 1024 x 16B (R12 bug: 512)
        int kk = idx4 >> 4, n4 = idx4 & 15;
        cp_async16(sbase + OFF_KS + (uint32_t)idx4*16, Kg0 + (size_t)kk*SS + n4*4);
    }
    for (int idx = tid; idx < 1024; idx += NTHR) {
        int row = idx >> 4, cc = idx & 15;
        cp_async16(sbase + OFF_VHI + (uint32_t)row*VROWB + cc*16, Vh0 + (size_t)row*DD + cc*8);
        cp_async16(sbase + OFF_VLO + (uint32_t)row*VROWB + cc*16, Vl0 + (size_t)row*DD + cc*8);
    }
    cp_commit();

    float mrow[8], lrow[8];       // WG-A state
    #pragma unroll
    for (int r = 0; r < 8; r++) { mrow[r] = -INFINITY; lrow[r] = 0.0f; }

    float c[128];                 // WG-B state: [dh][16 nt][4]
    #pragma unroll
    for (int i = 0; i < 128; i++) c[i] = 0.0f;

    // ---- peel kt = 0 ----
    cp_wait_all();
    __syncthreads();
    {   // prefetch K1
        const float* Kg = Kg0 + BN;
        uint32_t kd = sbase + OFF_KS + 16384;
        for (int idx4 = tid; idx4 < 1024; idx4 += NTHR) {
            int kk = idx4 >> 4, n4 = idx4 & 15;
            cp_async16(kd + (uint32_t)idx4*16, Kg + (size_t)kk*SS + n4*4);
        }
        cp_commit();
    }
    if (isA) {
        u64 acc2[4][4];
        #pragma unroll
        for (int mp = 0; mp < 4; mp++)
            #pragma unroll
            for (int n = 0; n < 4; n++) acc2[mp][n] = 0ULL;
        #pragma unroll
        for (int ks = 0; ks < 4; ks++)
            gemm1_chunk(QsT, (const float*)(smem + OFF_KS), ti, tj, ks, acc2);
        softmax_tile(acc2, mrow, lrow, smem, OFF_PHI, (float*)(smem + OFF_F), ti, tj);
    }
    {   // prefetch V1 (buffer 1 free; no barrier needed on first tile)
        const __nv_bfloat16* Vh = Vh0 + (size_t)BN*DD;
        const __nv_bfloat16* Vl = Vl0 + (size_t)BN*DD;
        for (int idx = tid; idx < 1024; idx += NTHR) {
            int row = idx >> 4, cc = idx & 15;
            cp_async16(sbase + OFF_VHI + VTILE + (uint32_t)row*VROWB + cc*16,
                       Vh + (size_t)row*DD + cc*8);
            cp_async16(sbase + OFF_VLO + VTILE + (uint32_t)row*VROWB + cc*16,
                       Vl + (size_t)row*DD + cc*8);
        }
        cp_commit();
    }

    // ---- main loop: kt = 1..31; WG-B works on tile kt-1 ----
    for (int kt = 1; kt < SS/BN; ++kt) {
        cp_wait_1();         // K[kt] + V[kt-1] done; newest group V[kt] may fly
        __syncthreads();     // orders P[kt-1]/f[kt-1] stores

        if (kt + 1 < SS/BN) {  // prefetch K[kt+1]
            const float* Kg = Kg0 + (kt + 1)*BN;
            uint32_t kd = sbase + OFF_KS + (uint32_t)((kt + 1) & 1)*16384;
            for (int idx4 = tid; idx4 < 1024; idx4 += NTHR) {
                int kk = idx4 >> 4, n4 = idx4 & 15;
                cp_async16(kd + (uint32_t)idx4*16, Kg + (size_t)kk*SS + n4*4);
            }
        }
        cp_commit();

        if (isA) {
            const float* KsT = (const float*)(smem + OFF_KS + (uint32_t)(kt & 1)*16384);
            u64 acc2[4][4];
            #pragma unroll
            for (int mp = 0; mp < 4; mp++)
                #pragma unroll
                for (int n = 0; n < 4; n++) acc2[mp][n] = 0ULL;
            #pragma unroll
            for (int ks = 0; ks < 4; ks++)
                gemm1_chunk(QsT, KsT, ti, tj, ks, acc2);
            __syncthreads();   // WG-B done reading V[kt-1]
            if (kt + 1 < SS/BN) {
                const __nv_bfloat16* Vh = Vh0 + (size_t)((kt + 1)*BN)*DD;
                const __nv_bfloat16* Vl = Vl0 + (size_t)((kt + 1)*BN)*DD;
                uint32_t vh = sbase + OFF_VHI + (uint32_t)((kt + 1) & 1)*VTILE;
                uint32_t vl = sbase + OFF_VLO + (uint32_t)((kt + 1) & 1)*VTILE;
                for (int idx = tid; idx < 1024; idx += NTHR) {
                    int row = idx >> 4, cc = idx & 15;
                    cp_async16(vh + (uint32_t)row*VROWB + cc*16, Vh + (size_t)row*DD + cc*8);
                    cp_async16(vl + (uint32_t)row*VROWB + cc*16, Vl + (size_t)row*DD + cc*8);
                }
            }
            cp_commit();
            softmax_tile(acc2, mrow, lrow, smem,
                         OFF_PHI + (uint32_t)(kt & 1)*PBUF,
                         (float*)(smem + OFF_F + (uint32_t)(kt & 1)*512), ti, tj);
        } else {
            const float* fprev = (const float*)(smem + OFF_F + (uint32_t)((kt - 1) & 1)*512);
            const uint32_t pa = pa_base + (uint32_t)((kt - 1) & 1)*PBUF;
            const uint32_t vb = vb_base + (uint32_t)((kt - 1) & 1)*VTILE;
            rescale_c2(c, fprev, rg, lane);
            #pragma unroll
            for (int ks = 0; ks < 4; ks++)
                gemm2_chunk2(pa, vb, ks, c);
            __syncthreads();   // matches WG-A's mid barrier
            if (kt + 1 < SS/BN) {
                const __nv_bfloat16* Vh = Vh0 + (size_t)((kt + 1)*BN)*DD;
                const __nv_bfloat16* Vl = Vl0 + (size_t)((kt + 1)*BN)*DD;
                uint32_t vh = sbase + OFF_VHI + (uint32_t)((kt + 1) & 1)*VTILE;
                uint32_t vl = sbase + OFF_VLO + (uint32_t)((kt + 1) & 1)*VTILE;
                for (int idx = tid; idx < 1024; idx += NTHR) {
                    int row = idx >> 4, cc = idx & 15;
                    cp_async16(vh + (uint32_t)row*VROWB + cc*16, Vh + (size_t)row*DD + cc*8);
                    cp_async16(vl + (uint32_t)row*VROWB + cc*16, Vl + (size_t)row*DD + cc*8);
                }
            }
            cp_commit();
        }
    }

    // ---- tail: GEMM2 for last tile (kt = 31) ----
    cp_wait_all();
    __syncthreads();   // P[31]/f[31] visible
    if (!isA) {
        const int lt = (SS/BN - 1) & 1;
        rescale_c2(c, (const float*)(smem + OFF_F + (uint32_t)lt*512), rg, lane);
        const uint32_t pa = pa_base + (uint32_t)lt*PBUF;
        const uint32_t vb = vb_base + (uint32_t)lt*VTILE;
        #pragma unroll
        for (int ks = 0; ks < 4; ks++)
            gemm2_chunk2(pa, vb, ks, c);
    }

    // ---- epilogue: WG-A publishes l, WG-B normalizes + stores ----
    if (isA && tj == 0) {
        #pragma unroll
        for (int r = 0; r < 8; r++) lptr[ti*8 + r] = lrow[r];
    }
    __syncthreads();
    if (!isA) {
        #pragma unroll
        for (int mt = 0; mt < 2; mt++) {
            int rloc = rg*32 + mt*16 + (lane >> 2);
            float il0 = 1.0f / lptr[rloc];
            float il1 = 1.0f / lptr[rloc + 8];
            int r0 = qt*BM + rloc;
            #pragma unroll
            for (int dh = 0; dh < 2; dh++) {
                float* op0 = out + (((size_t)b*SS + r0)*HH + h)*DD + dh*64 + (lane & 3)*2;
                float* op1 = op0 + (size_t)8*HH*DD;   // row+8 -> s+8
                #pragma unroll
                for (int nt = 0; nt < 8; nt++) {
                    int ci = dh*64 + (mt*8 + nt)*4;
                    *(float2*)(op0 + nt*8) = make_float2(c[ci + 0]*il0, c[ci + 1]*il0);
                    *(float2*)(op1 + nt*8) = make_float2(c[ci + 2]*il1, c[ci + 3]*il1);
                }
            }
        }
    }
}

extern "C" void kernel_launch(void* const* d_in, const int* in_sizes, int n_in,
                              void* d_out, int out_size) {
    const float* q = (const float*)d_in[0];
    const float* k = (const float*)d_in[1];
    const float* v = (const float*)d_in[2];
    float* out = (float*)d_out;

    cudaFuncSetAttribute(attn_kernel, cudaFuncAttributeMaxDynamicSharedMemorySize, SMEM_TOTAL);

    init_inv<<<1, 64>>>();
    dim3 pgrid(SS/64, HH, BB);
    prep_qk<<<pgrid, 256>>>(q, k);
    prep_v<<<pgrid, 256>>>(v);

    dim3 grid(SS/BM, HH, BB);
    attn_kernel<<<grid, NTHR, SMEM_TOTAL>>>(out);
}

// round 15
// speedup vs baseline: 1.5109x; 1.5109x over previous
#include <cuda_runtime.h>
#include <cuda_bf16.h>
#include <math.h>
#include <stdint.h>

#define BB 4
#define SS 2048
#define HH 16
#define DD 128
#define DH 64    // effective qk dim (first half, duplicated in reference)
#define BM 128
#define BN 64
#define NTHR 256

typedef unsigned long long u64;

// ---- scratch (no allocs allowed) ----
__device__ __nv_bfloat16 g_Qh[(size_t)BB*HH*SS*DH];  // [b,h,s,64] tri-split Q'
__device__ __nv_bfloat16 g_Qm[(size_t)BB*HH*SS*DH];
__device__ __nv_bfloat16 g_Ql[(size_t)BB*HH*SS*DH];
__device__ __nv_bfloat16 g_Kh[(size_t)BB*HH*DH*SS];  // [b,h,64,s] tri-split K' (k-major)
__device__ __nv_bfloat16 g_Km[(size_t)BB*HH*DH*SS];
__device__ __nv_bfloat16 g_Kl[(size_t)BB*HH*DH*SS];
__device__ __nv_bfloat16 g_Vhi[(size_t)BB*HH*SS*DD]; // [b,h,s,d] V hi/lo
__device__ __nv_bfloat16 g_Vlo[(size_t)BB*HH*SS*DD];
__device__ float g_inv[DH];

// ---- smem layout (bytes) ----
#define QROWB 144            // 144 ≡ 4 words mod 32 -> conflict-free ldmatrix
#define KROWB 144
#define VROWB 272
#define OFF_QH 0             // 3 x 128*144 = 55296 (h, m, l at +18432 each)
#define QSPL   18432
#define OFF_K  55296         // 2 buf x 3 x 64*144 = 55296
#define KSPL   9216
#define KBUF   27648
#define OFF_V  110592        // 2 buf x 2 x 64*272 = 69632
#define VSPL   17408
#define VBUF   34816
#define SMEM_TOTAL 180224

// ---------------- cp.async ----------------
__device__ __forceinline__ void cp_async16(uint32_t saddr, const void* gptr) {
    asm volatile("cp.async.cg.shared.global [%0], [%1], 16;" :: "r"(saddr), "l"(gptr));
}
__device__ __forceinline__ void cp_commit() { asm volatile("cp.async.commit_group;"); }
__device__ __forceinline__ void cp_wait_all() { asm volatile("cp.async.wait_group 0;"); }
__device__ __forceinline__ void cp_wait_1()  { asm volatile("cp.async.wait_group 1;"); }

// ---------------- tensor core: ldmatrix + mma.sync (base PTX) ----------------
__device__ __forceinline__ void ldmx4(uint32_t* r, uint32_t a) {
    asm volatile("ldmatrix.sync.aligned.m8n8.x4.shared.b16 {%0,%1,%2,%3}, [%4];"
        : "=r"(r[0]), "=r"(r[1]), "=r"(r[2]), "=r"(r[3]) : "r"(a));
}
__device__ __forceinline__ void ldmx4t(uint32_t* r, uint32_t a) {
    asm volatile("ldmatrix.sync.aligned.m8n8.x4.trans.shared.b16 {%0,%1,%2,%3}, [%4];"
        : "=r"(r[0]), "=r"(r[1]), "=r"(r[2]), "=r"(r[3]) : "r"(a));
}
__device__ __forceinline__ void mma2(float* c, const uint32_t* a, uint32_t b0, uint32_t b1) {
    asm volatile("mma.sync.aligned.m16n8k16.row.col.f32.bf16.bf16.f32 "
        "{%0,%1,%2,%3}, {%4,%5,%6,%7}, {%8,%9}, {%0,%1,%2,%3};"
        : "+f"(c[0]), "+f"(c[1]), "+f"(c[2]), "+f"(c[3])
        : "r"(a[0]), "r"(a[1]), "r"(a[2]), "r"(a[3]), "r"(b0), "r"(b1));
}

__device__ __forceinline__ uint32_t pk2(float lo, float hi) {
    __nv_bfloat162 t; t.x = __float2bfloat16(lo); t.y = __float2bfloat16(hi);
    return *(uint32_t*)&t;
}

// ---------------- prep ----------------
__global__ void init_inv() {
    int i = threadIdx.x;
    g_inv[i] = (float)exp(-(double)i * (9.210340371976184 / 64.0)); // ln(1e4)/64
}

// q,k [b,s,h,128] (first 64 dims) * fc -> Q tri-split [b,h,s,64], K tri-split [b,h,64,s]
__global__ void prep_qk(const float* __restrict__ q, const float* __restrict__ k) {
    __shared__ float ksm[64*65];
    const int st = blockIdx.x, h = blockIdx.y, b = blockIdx.z;
    const int tid = threadIdx.x;
    for (int idx = tid; idx < 64*64; idx += 256) {
        int sl = idx >> 6, i = idx & 63;
        int s = st*64 + sl;
        float fc = 2.0f * ((float)s * g_inv[i]);
        size_t gin = ((size_t)(b*SS + s)*HH + h)*DD + i;
        float xq = q[gin] * fc;
        __nv_bfloat16 qh = __float2bfloat16(xq);
        float rq = xq - __bfloat162float(qh);
        __nv_bfloat16 qm = __float2bfloat16(rq);
        __nv_bfloat16 ql = __float2bfloat16(rq - __bfloat162float(qm));
        size_t oq = ((size_t)(b*HH + h)*SS + s)*DH + i;
        g_Qh[oq] = qh; g_Qm[oq] = qm; g_Ql[oq] = ql;
        ksm[i*65 + sl] = k[gin] * fc;
    }
    __syncthreads();
    for (int idx = tid; idx < 64*64; idx += 256) {
        int i = idx >> 6, sl = idx & 63;
        float xk = ksm[i*65 + sl];
        __nv_bfloat16 kh = __float2bfloat16(xk);
        float rk = xk - __bfloat162float(kh);
        __nv_bfloat16 km = __float2bfloat16(rk);
        __nv_bfloat16 kl = __float2bfloat16(rk - __bfloat162float(km));
        size_t ok = ((size_t)(b*HH + h)*DH + i)*SS + st*64 + sl;
        g_Kh[ok] = kh; g_Km[ok] = km; g_Kl[ok] = kl;
    }
}

__global__ void prep_v(const float* __restrict__ v) {
    const int st = blockIdx.x, h = blockIdx.y, b = blockIdx.z;
    const int tid = threadIdx.x;
    for (int idx = tid; idx < 64*32; idx += 256) {
        int s = idx >> 5, d4 = idx & 31;
        float4 x = *(const float4*)&v[((size_t)(b*SS + st*64 + s)*HH + h)*DD + d4*4];
        __nv_bfloat16 h0 = __float2bfloat16(x.x), h1 = __float2bfloat16(x.y);
        __nv_bfloat16 h2 = __float2bfloat16(x.z), h3 = __float2bfloat16(x.w);
        __nv_bfloat16 l0 = __float2bfloat16(x.x - __bfloat162float(h0));
        __nv_bfloat16 l1 = __float2bfloat16(x.y - __bfloat162float(h1));
        __nv_bfloat16 l2 = __float2bfloat16(x.z - __bfloat162float(h2));
        __nv_bfloat16 l3 = __float2bfloat16(x.w - __bfloat162float(h3));
        size_t o = ((size_t)(b*HH + h)*SS + st*64 + s)*DD + d4*4;
        __nv_bfloat162* ph = (__nv_bfloat162*)(g_Vhi + o);
        __nv_bfloat162* pl = (__nv_bfloat162*)(g_Vlo + o);
        __nv_bfloat162 a; a.x = h0; a.y = h1; ph[0] = a;
        a.x = h2; a.y = h3; ph[1] = a;
        a.x = l0; a.y = l1; pl[0] = a;
        a.x = l2; a.y = l3; pl[1] = a;
    }
}

// ---------------- tile fills ----------------
__device__ __forceinline__ void fill_K(uint32_t sb, int buf, int kt, int tid,
                                       const __nv_bfloat16* Kh, const __nv_bfloat16* Km,
                                       const __nv_bfloat16* Kl) {
    uint32_t kd = sb + OFF_K + (uint32_t)buf*KBUF;
    #pragma unroll
    for (int it = 0; it < 2; it++) {
        int idx = tid + it*NTHR;
        int row = idx >> 3, cc = idx & 7;
        size_t so = (size_t)row*SS + kt*BN + cc*8;
        uint32_t d = kd + (uint32_t)row*KROWB + cc*16;
        cp_async16(d, Kh + so);
        cp_async16(d + KSPL, Km + so);
        cp_async16(d + 2*KSPL, Kl + so);
    }
}
__device__ __forceinline__ void fill_V(uint32_t sb, int buf, int kt, int tid,
                                       const __nv_bfloat16* Vh, const __nv_bfloat16* Vl) {
    uint32_t vd = sb + OFF_V + (uint32_t)buf*VBUF;
    #pragma unroll
    for (int it = 0; it < 4; it++) {
        int idx = tid + it*NTHR;
        int row = idx >> 4, cc = idx & 15;
        size_t so = (size_t)(kt*BN + row)*DD + cc*8;
        uint32_t d = vd + (uint32_t)row*VROWB + cc*16;
        cp_async16(d, Vh + so);
        cp_async16(d + VSPL, Vl + so);
    }
}

// ---------------- flash attention: all-tensor-core, P stays in registers ----------------
// 8 warps; warp w owns rows w*16..+15 for the whole pipeline (GEMM1, softmax, GEMM2).
// Only shared state: K/V tiles (one barrier pair per kt).
__global__ __launch_bounds__(NTHR, 1)
void attn_kernel(float* __restrict__ out) {
    extern __shared__ char smem[];
    const uint32_t sbase = (uint32_t)__cvta_generic_to_shared(smem);

    const int qt = blockIdx.x, h = blockIdx.y, b = blockIdx.z;
    const int tid = threadIdx.x;
    const int wid = tid >> 5, lane = tid & 31;

    const __nv_bfloat16* Qh_g = g_Qh + ((size_t)(b*HH + h)*SS + qt*BM)*DH;
    const __nv_bfloat16* Qm_g = g_Qm + ((size_t)(b*HH + h)*SS + qt*BM)*DH;
    const __nv_bfloat16* Ql_g = g_Ql + ((size_t)(b*HH + h)*SS + qt*BM)*DH;
    const __nv_bfloat16* Kh_g = g_Kh + (size_t)(b*HH + h)*DH*SS;
    const __nv_bfloat16* Km_g = g_Km + (size_t)(b*HH + h)*DH*SS;
    const __nv_bfloat16* Kl_g = g_Kl + (size_t)(b*HH + h)*DH*SS;
    const __nv_bfloat16* Vh_g = g_Vhi + (size_t)(b*HH + h)*SS*DD;
    const __nv_bfloat16* Vl_g = g_Vlo + (size_t)(b*HH + h)*SS*DD;

    // ---- prologue: Q (3 splits) + K0/V0, then K1/V1 ----
    {
        const __nv_bfloat16* qs[3] = {Qh_g, Qm_g, Ql_g};
        #pragma unroll
        for (int sp = 0; sp < 3; sp++)
            #pragma unroll
            for (int it = 0; it < 4; it++) {
                int idx = tid + it*NTHR;
                int row = idx >> 3, cc = idx & 7;
                cp_async16(sbase + OFF_QH + (uint32_t)sp*QSPL + (uint32_t)row*QROWB + cc*16,
                           qs[sp] + (size_t)row*DH + cc*8);
            }
    }
    fill_K(sbase, 0, 0, tid, Kh_g, Km_g, Kl_g);
    fill_V(sbase, 0, 0, tid, Vh_g, Vl_g);
    cp_commit();                       // G0
    fill_K(sbase, 1, 1, tid, Kh_g, Km_g, Kl_g);
    fill_V(sbase, 1, 1, tid, Vh_g, Vl_g);
    cp_commit();                       // G1
    cp_wait_1();                       // G0 done
    __syncthreads();

    // ---- Q fragments: load once, keep in registers ----
    uint32_t qh[4][4], qm[4][4], ql[4][4];
    {
        uint32_t qf = sbase + OFF_QH + (uint32_t)(wid*16 + (lane & 15))*QROWB
                    + ((lane >> 4) << 4);
        #pragma unroll
        for (int ks = 0; ks < 4; ks++) {
            ldmx4(qh[ks], qf + ks*32);
            ldmx4(qm[ks], qf + QSPL + ks*32);
            ldmx4(ql[ks], qf + 2*QSPL + ks*32);
        }
    }

    const float sc2 = 1.44269504088896340736f / 64.0f;  // log2(e)/64
    float mrow0 = -INFINITY, mrow1 = -INFINITY, lrow0 = 0.0f, lrow1 = 0.0f;
    float c[16][4];
    #pragma unroll
    for (int t = 0; t < 16; t++)
        #pragma unroll
        for (int j = 0; j < 4; j++) c[t][j] = 0.0f;

    const uint32_t kfb = sbase + OFF_K + (uint32_t)(lane & 15)*KROWB + ((lane >> 4) << 4);
    const uint32_t vfb = sbase + OFF_V + (uint32_t)(lane & 15)*VROWB + ((lane >> 4) << 4);

    for (int kt = 0; kt < SS/BN; ++kt) {
        const int buf = kt & 1;
        const uint32_t kb = kfb + (uint32_t)buf*KBUF;
        const uint32_t vb = vfb + (uint32_t)buf*VBUF;

        // ---- GEMM1 (tensor): S = Q'K'^T via tri-split bf16, 6 terms ----
        float s[8][4];
        #pragma unroll
        for (int t = 0; t < 8; t++)
            #pragma unroll
            for (int j = 0; j < 4; j++) s[t][j] = 0.0f;

        #pragma unroll
        for (int ks = 0; ks < 4; ks++) {
            #pragma unroll
            for (int nb = 0; nb < 4; nb++) {
                uint32_t ka = kb + (uint32_t)(ks*16)*KROWB + nb*32;
                uint32_t kh4[4], km4[4], kl4[4];
                ldmx4t(kh4, ka);
                ldmx4t(km4, ka + KSPL);
                ldmx4t(kl4, ka + 2*KSPL);
                float* s0 = s[2*nb];
                float* s1 = s[2*nb + 1];
                mma2(s0, qh[ks], kh4[0], kh4[1]); mma2(s1, qh[ks], kh4[2], kh4[3]);
                mma2(s0, qh[ks], km4[0], km4[1]); mma2(s1, qh[ks], km4[2], km4[3]);
                mma2(s0, qm[ks], kh4[0], kh4[1]); mma2(s1, qm[ks], kh4[2], kh4[3]);
                mma2(s0, qh[ks], kl4[0], kl4[1]); mma2(s1, qh[ks], kl4[2], kl4[3]);
                mma2(s0, ql[ks], kh4[0], kh4[1]); mma2(s1, ql[ks], kh4[2], kh4[3]);
                mma2(s0, qm[ks], km4[0], km4[1]); mma2(s1, qm[ks], km4[2], km4[3]);
            }
        }

        // ---- softmax in registers (rows r0 = wid*16+(lane>>2), r1 = r0+8) ----
        float mx0 = -INFINITY, mx1 = -INFINITY;
        #pragma unroll
        for (int t = 0; t < 8; t++) {
            mx0 = fmaxf(mx0, fmaxf(s[t][0], s[t][1]));
            mx1 = fmaxf(mx1, fmaxf(s[t][2], s[t][3]));
        }
        mx0 = fmaxf(mx0, __shfl_xor_sync(0xffffffffu, mx0, 1));
        mx0 = fmaxf(mx0, __shfl_xor_sync(0xffffffffu, mx0, 2));
        mx1 = fmaxf(mx1, __shfl_xor_sync(0xffffffffu, mx1, 1));
        mx1 = fmaxf(mx1, __shfl_xor_sync(0xffffffffu, mx1, 2));

        float mn0 = fmaxf(mrow0, mx0*sc2);
        float mn1 = fmaxf(mrow1, mx1*sc2);
        float f0 = exp2f(mrow0 - mn0);   // 0 on first tile
        float f1 = exp2f(mrow1 - mn1);
        mrow0 = mn0; mrow1 = mn1;

        uint32_t ph[4][4], pl[4][4];
        float sum0 = 0.0f, sum1 = 0.0f;
        #pragma unroll
        for (int t = 0; t < 8; t++) {
            float p0 = exp2f(fmaf(s[t][0], sc2, -mn0));
            float p1 = exp2f(fmaf(s[t][1], sc2, -mn0));
            float p2 = exp2f(fmaf(s[t][2], sc2, -mn1));
            float p3 = exp2f(fmaf(s[t][3], sc2, -mn1));
            sum0 += p0 + p1; sum1 += p2 + p3;
            float h0 = __bfloat162float(__float2bfloat16(p0));
            float h1 = __bfloat162float(__float2bfloat16(p1));
            float h2 = __bfloat162float(__float2bfloat16(p2));
            float h3 = __bfloat162float(__float2bfloat16(p3));
            int ks = t >> 1, off = (t & 1)*2;
            ph[ks][off]     = pk2(h0, h1);
            ph[ks][off + 1] = pk2(h2, h3);
            pl[ks][off]     = pk2(p0 - h0, p1 - h1);
            pl[ks][off + 1] = pk2(p2 - h2, p3 - h3);
        }
        sum0 += __shfl_xor_sync(0xffffffffu, sum0, 1);
        sum0 += __shfl_xor_sync(0xffffffffu, sum0, 2);
        sum1 += __shfl_xor_sync(0xffffffffu, sum1, 1);
        sum1 += __shfl_xor_sync(0xffffffffu, sum1, 2);
        lrow0 = lrow0*f0 + sum0;
        lrow1 = lrow1*f1 + sum1;

        // rescale running O
        #pragma unroll
        for (int t = 0; t < 16; t++) {
            c[t][0] *= f0; c[t][1] *= f0;
            c[t][2] *= f1; c[t][3] *= f1;
        }

        // ---- GEMM2 (tensor): O += Ph*Vh + Ph*Vl + Pl*Vh ----
        #pragma unroll
        for (int ks = 0; ks < 4; ks++) {
            #pragma unroll
            for (int db = 0; db < 8; db++) {
                uint32_t va = vb + (uint32_t)(ks*16)*VROWB + db*32;
                uint32_t vh4[4], vl4[4];
                ldmx4t(vh4, va);
                ldmx4t(vl4, va + VSPL);
                float* c0 = c[2*db];
                float* c1 = c[2*db + 1];
                mma2(c0, ph[ks], vh4[0], vh4[1]); mma2(c1, ph[ks], vh4[2], vh4[3]);
                mma2(c0, ph[ks], vl4[0], vl4[1]); mma2(c1, ph[ks], vl4[2], vl4[3]);
                mma2(c0, pl[ks], vh4[0], vh4[1]); mma2(c1, pl[ks], vh4[2], vh4[3]);
            }
        }

        if (kt == SS/BN - 1) break;
        __syncthreads();                      // all warps done with buf kt&1
        if (kt + 2 < SS/BN) {
            fill_K(sbase, buf, kt + 2, tid, Kh_g, Km_g, Kl_g);
            fill_V(sbase, buf, kt + 2, tid, Vh_g, Vl_g);
        }
        cp_commit();
        cp_wait_1();                          // tile kt+1 resident
        __syncthreads();                      // visible to all warps
    }

    // ---- epilogue: normalize + store ----
    {
        float il0 = 1.0f / lrow0;
        float il1 = 1.0f / lrow1;
        int r0 = qt*BM + wid*16 + (lane >> 2);
        float* op0 = out + (((size_t)b*SS + r0)*HH + h)*DD + (lane & 3)*2;
        float* op1 = op0 + (size_t)8*HH*DD;   // row+8 -> s+8
        #pragma unroll
        for (int t = 0; t < 16; t++) {
            *(float2*)(op0 + t*8) = make_float2(c[t][0]*il0, c[t][1]*il0);
            *(float2*)(op1 + t*8) = make_float2(c[t][2]*il1, c[t][3]*il1);
        }
    }
}

extern "C" void kernel_launch(void* const* d_in, const int* in_sizes, int n_in,
                              void* d_out, int out_size) {
    const float* q = (const float*)d_in[0];
    const float* k = (const float*)d_in[1];
    const float* v = (const float*)d_in[2];
    float* out = (float*)d_out;

    cudaFuncSetAttribute(attn_kernel, cudaFuncAttributeMaxDynamicSharedMemorySize, SMEM_TOTAL);

    init_inv<<<1, 64>>>();
    dim3 pgrid(SS/64, HH, BB);
    prep_qk<<<pgrid, 256>>>(q, k);
    prep_v<<<pgrid, 256>>>(v);

    dim3 grid(SS/BM, HH, BB);
    attn_kernel<<<grid, NTHR, SMEM_TOTAL>>>(out);
}

// round 16
// speedup vs baseline: 2.0996x; 1.3896x over previous
#include <cuda_runtime.h>
#include <cuda_bf16.h>
#include <math.h>
#include <stdint.h>

#define BB 4
#define SS 2048
#define HH 16
#define DD 128
#define DH 64    // effective qk dim (first half, duplicated in reference)
#define BM 128
#define BN 64
#define NT (SS/BN)
#define NTHR 256

typedef unsigned long long u64;

// ---- scratch (no allocs allowed) ----
__device__ __nv_bfloat16 g_Qh[(size_t)BB*HH*SS*DH];  // [b,h,s,64] tri-split Q'
__device__ __nv_bfloat16 g_Qm[(size_t)BB*HH*SS*DH];
__device__ __nv_bfloat16 g_Ql[(size_t)BB*HH*SS*DH];
__device__ __nv_bfloat16 g_Kh[(size_t)BB*HH*DH*SS];  // [b,h,64,s] tri-split K' (k-major)
__device__ __nv_bfloat16 g_Km[(size_t)BB*HH*DH*SS];
__device__ __nv_bfloat16 g_Kl[(size_t)BB*HH*DH*SS];
__device__ __nv_bfloat16 g_Vhi[(size_t)BB*HH*SS*DD]; // [b,h,s,d] V hi/lo
__device__ __nv_bfloat16 g_Vlo[(size_t)BB*HH*SS*DD];
__device__ float g_inv[DH];

// ---- smem layout (bytes) ----
#define QROWB 144            // 144 ≡ 4 words mod 32 -> conflict-free ldmatrix
#define KROWB 144
#define VROWB 272
#define OFF_QH 0             // 3 x 128*144 = 55296 (h, m, l at +18432 each)
#define QSPL   18432
#define OFF_K  55296         // 2 buf x 3 x 64*144 = 55296
#define KSPL   9216
#define KBUF   27648
#define OFF_V  110592        // 2 buf x 2 x 64*272 = 69632
#define VSPL   17408
#define VBUF   34816
#define SMEM_TOTAL 180224

// ---------------- cp.async ----------------
__device__ __forceinline__ void cp_async16(uint32_t saddr, const void* gptr) {
    asm volatile("cp.async.cg.shared.global [%0], [%1], 16;" :: "r"(saddr), "l"(gptr));
}
__device__ __forceinline__ void cp_commit() { asm volatile("cp.async.commit_group;"); }
__device__ __forceinline__ void cp_wait_1()  { asm volatile("cp.async.wait_group 1;"); }

// ---------------- tensor core: ldmatrix + mma.sync (base PTX) ----------------
__device__ __forceinline__ void ldmx4(uint32_t* r, uint32_t a) {
    asm volatile("ldmatrix.sync.aligned.m8n8.x4.shared.b16 {%0,%1,%2,%3}, [%4];"
        : "=r"(r[0]), "=r"(r[1]), "=r"(r[2]), "=r"(r[3]) : "r"(a));
}
__device__ __forceinline__ void ldmx4t(uint32_t* r, uint32_t a) {
    asm volatile("ldmatrix.sync.aligned.m8n8.x4.trans.shared.b16 {%0,%1,%2,%3}, [%4];"
        : "=r"(r[0]), "=r"(r[1]), "=r"(r[2]), "=r"(r[3]) : "r"(a));
}
__device__ __forceinline__ void mma2(float* c, const uint32_t* a, uint32_t b0, uint32_t b1) {
    asm volatile("mma.sync.aligned.m16n8k16.row.col.f32.bf16.bf16.f32 "
        "{%0,%1,%2,%3}, {%4,%5,%6,%7}, {%8,%9}, {%0,%1,%2,%3};"
        : "+f"(c[0]), "+f"(c[1]), "+f"(c[2]), "+f"(c[3])
        : "r"(a[0]), "r"(a[1]), "r"(a[2]), "r"(a[3]), "r"(b0), "r"(b1));
}

__device__ __forceinline__ uint32_t pk2(float lo, float hi) {
    __nv_bfloat162 t; t.x = __float2bfloat16(lo); t.y = __float2bfloat16(hi);
    return *(uint32_t*)&t;
}

// ---------------- prep ----------------
__global__ void init_inv() {
    int i = threadIdx.x;
    g_inv[i] = (float)exp(-(double)i * (9.210340371976184 / 64.0)); // ln(1e4)/64
}

// q,k [b,s,h,128] (first 64 dims) * fc -> Q tri-split [b,h,s,64], K tri-split [b,h,64,s]
__global__ void prep_qk(const float* __restrict__ q, const float* __restrict__ k) {
    __shared__ float ksm[64*65];
    const int st = blockIdx.x, h = blockIdx.y, b = blockIdx.z;
    const int tid = threadIdx.x;
    for (int idx = tid; idx < 64*64; idx += 256) {
        int sl = idx >> 6, i = idx & 63;
        int s = st*64 + sl;
        float fc = 2.0f * ((float)s * g_inv[i]);
        size_t gin = ((size_t)(b*SS + s)*HH + h)*DD + i;
        float xq = q[gin] * fc;
        __nv_bfloat16 qh = __float2bfloat16(xq);
        float rq = xq - __bfloat162float(qh);
        __nv_bfloat16 qm = __float2bfloat16(rq);
        __nv_bfloat16 ql = __float2bfloat16(rq - __bfloat162float(qm));
        size_t oq = ((size_t)(b*HH + h)*SS + s)*DH + i;
        g_Qh[oq] = qh; g_Qm[oq] = qm; g_Ql[oq] = ql;
        ksm[i*65 + sl] = k[gin] * fc;
    }
    __syncthreads();
    for (int idx = tid; idx < 64*64; idx += 256) {
        int i = idx >> 6, sl = idx & 63;
        float xk = ksm[i*65 + sl];
        __nv_bfloat16 kh = __float2bfloat16(xk);
        float rk = xk - __bfloat162float(kh);
        __nv_bfloat16 km = __float2bfloat16(rk);
        __nv_bfloat16 kl = __float2bfloat16(rk - __bfloat162float(km));
        size_t ok = ((size_t)(b*HH + h)*DH + i)*SS + st*64 + sl;
        g_Kh[ok] = kh; g_Km[ok] = km; g_Kl[ok] = kl;
    }
}

__global__ void prep_v(const float* __restrict__ v) {
    const int st = blockIdx.x, h = blockIdx.y, b = blockIdx.z;
    const int tid = threadIdx.x;
    for (int idx = tid; idx < 64*32; idx += 256) {
        int s = idx >> 5, d4 = idx & 31;
        float4 x = *(const float4*)&v[((size_t)(b*SS + st*64 + s)*HH + h)*DD + d4*4];
        __nv_bfloat16 h0 = __float2bfloat16(x.x), h1 = __float2bfloat16(x.y);
        __nv_bfloat16 h2 = __float2bfloat16(x.z), h3 = __float2bfloat16(x.w);
        __nv_bfloat16 l0 = __float2bfloat16(x.x - __bfloat162float(h0));
        __nv_bfloat16 l1 = __float2bfloat16(x.y - __bfloat162float(h1));
        __nv_bfloat16 l2 = __float2bfloat16(x.z - __bfloat162float(h2));
        __nv_bfloat16 l3 = __float2bfloat16(x.w - __bfloat162float(h3));
        size_t o = ((size_t)(b*HH + h)*SS + st*64 + s)*DD + d4*4;
        __nv_bfloat162* ph = (__nv_bfloat162*)(g_Vhi + o);
        __nv_bfloat162* pl = (__nv_bfloat162*)(g_Vlo + o);
        __nv_bfloat162 a; a.x = h0; a.y = h1; ph[0] = a;
        a.x = h2; a.y = h3; ph[1] = a;
        a.x = l0; a.y = l1; pl[0] = a;
        a.x = l2; a.y = l3; pl[1] = a;
    }
}

// ---------------- tile fills ----------------
__device__ __forceinline__ void fill_K(uint32_t sb, int buf, int kt, int tid,
                                       const __nv_bfloat16* Kh, const __nv_bfloat16* Km,
                                       const __nv_bfloat16* Kl) {
    uint32_t kd = sb + OFF_K + (uint32_t)buf*KBUF;
    #pragma unroll
    for (int it = 0; it < 2; it++) {
        int idx = tid + it*NTHR;
        int row = idx >> 3, cc = idx & 7;
        size_t so = (size_t)row*SS + kt*BN + cc*8;
        uint32_t d = kd + (uint32_t)row*KROWB + cc*16;
        cp_async16(d, Kh + so);
        cp_async16(d + KSPL, Km + so);
        cp_async16(d + 2*KSPL, Kl + so);
    }
}
__device__ __forceinline__ void fill_V(uint32_t sb, int buf, int kt, int tid,
                                       const __nv_bfloat16* Vh, const __nv_bfloat16* Vl) {
    uint32_t vd = sb + OFF_V + (uint32_t)buf*VBUF;
    #pragma unroll
    for (int it = 0; it < 4; it++) {
        int idx = tid + it*NTHR;
        int row = idx >> 4, cc = idx & 15;
        size_t so = (size_t)(kt*BN + row)*DD + cc*8;
        uint32_t d = vd + (uint32_t)row*VROWB + cc*16;
        cp_async16(d, Vh + so);
        cp_async16(d + VSPL, Vl + so);
    }
}

// ---------------- flash attention: all-tensor-core, REVERSE tile order + skip ----------
// 8 warps; warp w owns rows w*16..+15 end-to-end. Key tiles processed s2 high -> low:
// running max locks in early; dead tiles (all 16 rows < mrow-40) skip softmax+GEMM2
// exactly (their weights are < 2^-40 of the running l -> mathematically negligible).
__global__ __launch_bounds__(NTHR, 1)
void attn_kernel(float* __restrict__ out) {
    extern __shared__ char smem[];
    const uint32_t sbase = (uint32_t)__cvta_generic_to_shared(smem);

    const int qt = blockIdx.x, h = blockIdx.y, b = blockIdx.z;
    const int tid = threadIdx.x;
    const int wid = tid >> 5, lane = tid & 31;

    const __nv_bfloat16* Qh_g = g_Qh + ((size_t)(b*HH + h)*SS + qt*BM)*DH;
    const __nv_bfloat16* Qm_g = g_Qm + ((size_t)(b*HH + h)*SS + qt*BM)*DH;
    const __nv_bfloat16* Ql_g = g_Ql + ((size_t)(b*HH + h)*SS + qt*BM)*DH;
    const __nv_bfloat16* Kh_g = g_Kh + (size_t)(b*HH + h)*DH*SS;
    const __nv_bfloat16* Km_g = g_Km + (size_t)(b*HH + h)*DH*SS;
    const __nv_bfloat16* Kl_g = g_Kl + (size_t)(b*HH + h)*DH*SS;
    const __nv_bfloat16* Vh_g = g_Vhi + (size_t)(b*HH + h)*SS*DD;
    const __nv_bfloat16* Vl_g = g_Vlo + (size_t)(b*HH + h)*SS*DD;

    // ---- prologue: Q (3 splits) + tiles NT-1, NT-2 ----
    {
        const __nv_bfloat16* qs[3] = {Qh_g, Qm_g, Ql_g};
        #pragma unroll
        for (int sp = 0; sp < 3; sp++)
            #pragma unroll
            for (int it = 0; it < 4; it++) {
                int idx = tid + it*NTHR;
                int row = idx >> 3, cc = idx & 7;
                cp_async16(sbase + OFF_QH + (uint32_t)sp*QSPL + (uint32_t)row*QROWB + cc*16,
                           qs[sp] + (size_t)row*DH + cc*8);
            }
    }
    fill_K(sbase, (NT-1) & 1, NT-1, tid, Kh_g, Km_g, Kl_g);
    fill_V(sbase, (NT-1) & 1, NT-1, tid, Vh_g, Vl_g);
    cp_commit();
    fill_K(sbase, (NT-2) & 1, NT-2, tid, Kh_g, Km_g, Kl_g);
    fill_V(sbase, (NT-2) & 1, NT-2, tid, Vh_g, Vl_g);
    cp_commit();
    cp_wait_1();                       // tile NT-1 resident
    __syncthreads();

    // ---- Q fragments: load once, keep in registers ----
    uint32_t qh[4][4], qm[4][4], ql[4][4];
    {
        uint32_t qf = sbase + OFF_QH + (uint32_t)(wid*16 + (lane & 15))*QROWB
                    + ((lane >> 4) << 4);
        #pragma unroll
        for (int ks = 0; ks < 4; ks++) {
            ldmx4(qh[ks], qf + ks*32);
            ldmx4(qm[ks], qf + QSPL + ks*32);
            ldmx4(ql[ks], qf + 2*QSPL + ks*32);
        }
    }

    const float sc2 = 1.44269504088896340736f / 64.0f;  // log2(e)/64
    float mrow0 = -INFINITY, mrow1 = -INFINITY, lrow0 = 0.0f, lrow1 = 0.0f;
    float c[16][4];
    #pragma unroll
    for (int t = 0; t < 16; t++)
        #pragma unroll
        for (int j = 0; j < 4; j++) c[t][j] = 0.0f;

    const uint32_t kfb = sbase + OFF_K + (uint32_t)(lane & 15)*KROWB + ((lane >> 4) << 4);
    const uint32_t vfb = sbase + OFF_V + (uint32_t)(lane & 15)*VROWB + ((lane >> 4) << 4);

    for (int kt = NT - 1; kt >= 0; --kt) {
        const int buf = kt & 1;
        const uint32_t kb = kfb + (uint32_t)buf*KBUF;
        const uint32_t vb = vfb + (uint32_t)buf*VBUF;

        // ---- GEMM1 (tensor): S = Q'K'^T via tri-split bf16, 6 terms ----
        float s[8][4];
        #pragma unroll
        for (int t = 0; t < 8; t++)
            #pragma unroll
            for (int j = 0; j < 4; j++) s[t][j] = 0.0f;

        #pragma unroll
        for (int ks = 0; ks < 4; ks++) {
            #pragma unroll
            for (int nb = 0; nb < 4; nb++) {
                uint32_t ka = kb + (uint32_t)(ks*16)*KROWB + nb*32;
                uint32_t kh4[4], km4[4], kl4[4];
                ldmx4t(kh4, ka);
                ldmx4t(km4, ka + KSPL);
                ldmx4t(kl4, ka + 2*KSPL);
                float* s0 = s[2*nb];
                float* s1 = s[2*nb + 1];
                mma2(s0, qh[ks], kh4[0], kh4[1]); mma2(s1, qh[ks], kh4[2], kh4[3]);
                mma2(s0, qh[ks], km4[0], km4[1]); mma2(s1, qh[ks], km4[2], km4[3]);
                mma2(s0, qm[ks], kh4[0], kh4[1]); mma2(s1, qm[ks], kh4[2], kh4[3]);
                mma2(s0, qh[ks], kl4[0], kl4[1]); mma2(s1, qh[ks], kl4[2], kl4[3]);
                mma2(s0, ql[ks], kh4[0], kh4[1]); mma2(s1, ql[ks], kh4[2], kh4[3]);
                mma2(s0, qm[ks], km4[0], km4[1]); mma2(s1, qm[ks], km4[2], km4[3]);
            }
        }

        // ---- row max + liveness vote (rows r0 = wid*16+(lane>>2), r1 = r0+8) ----
        float mx0 = -INFINITY, mx1 = -INFINITY;
        #pragma unroll
        for (int t = 0; t < 8; t++) {
            mx0 = fmaxf(mx0, fmaxf(s[t][0], s[t][1]));
            mx1 = fmaxf(mx1, fmaxf(s[t][2], s[t][3]));
        }
        mx0 = fmaxf(mx0, __shfl_xor_sync(0xffffffffu, mx0, 1));
        mx0 = fmaxf(mx0, __shfl_xor_sync(0xffffffffu, mx0, 2));
        mx1 = fmaxf(mx1, __shfl_xor_sync(0xffffffffu, mx1, 1));
        mx1 = fmaxf(mx1, __shfl_xor_sync(0xffffffffu, mx1, 2));

        // tile dead for a row if its max logit2 <= mrow - 40 (weight < 2^-40 of l)
        bool livelane = (mx0*sc2 > mrow0 - 40.0f) || (mx1*sc2 > mrow1 - 40.0f);
        if (__any_sync(0xffffffffu, livelane)) {
            float mn0 = fmaxf(mrow0, mx0*sc2);
            float mn1 = fmaxf(mrow1, mx1*sc2);
            float f0 = exp2f(mrow0 - mn0);   // 0 on first tile
            float f1 = exp2f(mrow1 - mn1);
            mrow0 = mn0; mrow1 = mn1;

            uint32_t ph[4][4], pl[4][4];
            float sum0 = 0.0f, sum1 = 0.0f;
            #pragma unroll
            for (int t = 0; t < 8; t++) {
                float p0 = exp2f(fmaf(s[t][0], sc2, -mn0));
                float p1 = exp2f(fmaf(s[t][1], sc2, -mn0));
                float p2 = exp2f(fmaf(s[t][2], sc2, -mn1));
                float p3 = exp2f(fmaf(s[t][3], sc2, -mn1));
                sum0 += p0 + p1; sum1 += p2 + p3;
                float h0 = __bfloat162float(__float2bfloat16(p0));
                float h1 = __bfloat162float(__float2bfloat16(p1));
                float h2 = __bfloat162float(__float2bfloat16(p2));
                float h3 = __bfloat162float(__float2bfloat16(p3));
                int ks = t >> 1, off = (t & 1)*2;
                ph[ks][off]     = pk2(h0, h1);
                ph[ks][off + 1] = pk2(h2, h3);
                pl[ks][off]     = pk2(p0 - h0, p1 - h1);
                pl[ks][off + 1] = pk2(p2 - h2, p3 - h3);
            }
            sum0 += __shfl_xor_sync(0xffffffffu, sum0, 1);
            sum0 += __shfl_xor_sync(0xffffffffu, sum0, 2);
            sum1 += __shfl_xor_sync(0xffffffffu, sum1, 1);
            sum1 += __shfl_xor_sync(0xffffffffu, sum1, 2);
            lrow0 = lrow0*f0 + sum0;
            lrow1 = lrow1*f1 + sum1;

            // rescale running O
            #pragma unroll
            for (int t = 0; t < 16; t++) {
                c[t][0] *= f0; c[t][1] *= f0;
                c[t][2] *= f1; c[t][3] *= f1;
            }

            // ---- GEMM2 (tensor): O += Ph*Vh + Ph*Vl + Pl*Vh ----
            #pragma unroll
            for (int ks = 0; ks < 4; ks++) {
                #pragma unroll
                for (int db = 0; db < 8; db++) {
                    uint32_t va = vb + (uint32_t)(ks*16)*VROWB + db*32;
                    uint32_t vh4[4], vl4[4];
                    ldmx4t(vh4, va);
                    ldmx4t(vl4, va + VSPL);
                    float* c0 = c[2*db];
                    float* c1 = c[2*db + 1];
                    mma2(c0, ph[ks], vh4[0], vh4[1]); mma2(c1, ph[ks], vh4[2], vh4[3]);
                    mma2(c0, ph[ks], vl4[0], vl4[1]); mma2(c1, ph[ks], vl4[2], vl4[3]);
                    mma2(c0, pl[ks], vh4[0], vh4[1]); mma2(c1, pl[ks], vh4[2], vh4[3]);
                }
            }
        }

        if (kt == 0) break;
        __syncthreads();                      // all warps done with buf kt&1
        if (kt - 2 >= 0) {
            fill_K(sbase, buf, kt - 2, tid, Kh_g, Km_g, Kl_g);
            fill_V(sbase, buf, kt - 2, tid, Vh_g, Vl_g);
        }
        cp_commit();
        cp_wait_1();                          // tile kt-1 resident
        __syncthreads();                      // visible to all warps
    }

    // ---- epilogue: normalize + store ----
    {
        float il0 = 1.0f / lrow0;
        float il1 = 1.0f / lrow1;
        int r0 = qt*BM + wid*16 + (lane >> 2);
        float* op0 = out + (((size_t)b*SS + r0)*HH + h)*DD + (lane & 3)*2;
        float* op1 = op0 + (size_t)8*HH*DD;   // row+8 -> s+8
        #pragma unroll
        for (int t = 0; t < 16; t++) {
            *(float2*)(op0 + t*8) = make_float2(c[t][0]*il0, c[t][1]*il0);
            *(float2*)(op1 + t*8) = make_float2(c[t][2]*il1, c[t][3]*il1);
        }
    }
}

extern "C" void kernel_launch(void* const* d_in, const int* in_sizes, int n_in,
                              void* d_out, int out_size) {
    const float* q = (const float*)d_in[0];
    const float* k = (const float*)d_in[1];
    const float* v = (const float*)d_in[2];
    float* out = (float*)d_out;

    cudaFuncSetAttribute(attn_kernel, cudaFuncAttributeMaxDynamicSharedMemorySize, SMEM_TOTAL);

    init_inv<<<1, 64>>>();
    dim3 pgrid(SS/64, HH, BB);
    prep_qk<<<pgrid, 256>>>(q, k);
    prep_v<<<pgrid, 256>>>(v);

    dim3 grid(SS/BM, HH, BB);
    attn_kernel<<<grid, NTHR, SMEM_TOTAL>>>(out);
}

// round 17
// speedup vs baseline: 2.4680x; 1.1754x over previous
#include <cuda_runtime.h>
#include <cuda_bf16.h>
#include <math.h>
#include <stdint.h>

#define BB 4
#define SS 2048
#define HH 16
#define DD 128
#define DH 64    // effective qk dim (first half, duplicated in reference)
#define BM 128
#define BN 64
#define NT (SS/BN)
#define NTHR 256

typedef unsigned long long u64;

// ---- scratch (no allocs allowed) ----
__device__ __nv_bfloat16 g_Qh[(size_t)BB*HH*SS*DH];  // [b,h,s,64] tri-split Q'
__device__ __nv_bfloat16 g_Qm[(size_t)BB*HH*SS*DH];
__device__ __nv_bfloat16 g_Ql[(size_t)BB*HH*SS*DH];
__device__ __nv_bfloat16 g_Kh[(size_t)BB*HH*DH*SS];  // [b,h,64,s] tri-split K' (k-major)
__device__ __nv_bfloat16 g_Km[(size_t)BB*HH*DH*SS];
__device__ __nv_bfloat16 g_Kl[(size_t)BB*HH*DH*SS];
__device__ __nv_bfloat16 g_Vhi[(size_t)BB*HH*SS*DD]; // [b,h,s,d] V hi/lo
__device__ __nv_bfloat16 g_Vlo[(size_t)BB*HH*SS*DD];
__device__ float g_Qn[(size_t)BB*HH*SS];             // ||q'_row||  per row
__device__ float g_Kn[(size_t)BB*HH*NT];             // max ||k'_col|| per key tile
__device__ float g_inv[DH];

// ---- smem layout (bytes) ----
#define QROWB 144            // 144 ≡ 4 words mod 32 -> conflict-free ldmatrix
#define KROWB 144
#define VROWB 272
#define OFF_QH 0             // 3 x 128*144 = 55296 (h, m, l at +18432 each)
#define QSPL   18432
#define OFF_K  55296         // 2 buf x 3 x 64*144 = 55296
#define KSPL   9216
#define KBUF   27648
#define OFF_V  110592        // 2 buf x 2 x 64*272 = 69632
#define VSPL   17408
#define VBUF   34816
#define OFF_KN 180224        // float Kn[NT]
#define SMEM_TOTAL 180352

// ---------------- cp.async ----------------
__device__ __forceinline__ void cp_async16(uint32_t saddr, const void* gptr) {
    asm volatile("cp.async.cg.shared.global [%0], [%1], 16;" :: "r"(saddr), "l"(gptr));
}
__device__ __forceinline__ void cp_commit() { asm volatile("cp.async.commit_group;"); }
__device__ __forceinline__ void cp_wait_1()  { asm volatile("cp.async.wait_group 1;"); }

// ---------------- tensor core: ldmatrix + mma.sync (base PTX) ----------------
__device__ __forceinline__ void ldmx4(uint32_t* r, uint32_t a) {
    asm volatile("ldmatrix.sync.aligned.m8n8.x4.shared.b16 {%0,%1,%2,%3}, [%4];"
        : "=r"(r[0]), "=r"(r[1]), "=r"(r[2]), "=r"(r[3]) : "r"(a));
}
__device__ __forceinline__ void ldmx4t(uint32_t* r, uint32_t a) {
    asm volatile("ldmatrix.sync.aligned.m8n8.x4.trans.shared.b16 {%0,%1,%2,%3}, [%4];"
        : "=r"(r[0]), "=r"(r[1]), "=r"(r[2]), "=r"(r[3]) : "r"(a));
}
__device__ __forceinline__ void mma2(float* c, const uint32_t* a, uint32_t b0, uint32_t b1) {
    asm volatile("mma.sync.aligned.m16n8k16.row.col.f32.bf16.bf16.f32 "
        "{%0,%1,%2,%3}, {%4,%5,%6,%7}, {%8,%9}, {%0,%1,%2,%3};"
        : "+f"(c[0]), "+f"(c[1]), "+f"(c[2]), "+f"(c[3])
        : "r"(a[0]), "r"(a[1]), "r"(a[2]), "r"(a[3]), "r"(b0), "r"(b1));
}

__device__ __forceinline__ uint32_t pk2(float lo, float hi) {
    __nv_bfloat162 t; t.x = __float2bfloat16(lo); t.y = __float2bfloat16(hi);
    return *(uint32_t*)&t;
}

// ---------------- prep ----------------
__global__ void init_inv() {
    int i = threadIdx.x;
    g_inv[i] = (float)exp(-(double)i * (9.210340371976184 / 64.0)); // ln(1e4)/64
}

// q,k [b,s,h,128] (first 64 dims) * fc -> Q tri-split [b,h,s,64], K tri-split [b,h,64,s],
// plus row norms ||q'|| and per-tile max ||k'||.
__global__ void prep_qk(const float* __restrict__ q, const float* __restrict__ k) {
    __shared__ float qsm[64*65];
    __shared__ float ksm[64*65];
    __shared__ float kcol[64];
    const int st = blockIdx.x, h = blockIdx.y, b = blockIdx.z;
    const int tid = threadIdx.x;
    for (int idx = tid; idx < 64*64; idx += 256) {
        int sl = idx >> 6, i = idx & 63;
        int s = st*64 + sl;
        float fc = 2.0f * ((float)s * g_inv[i]);
        size_t gin = ((size_t)(b*SS + s)*HH + h)*DD + i;
        float xq = q[gin] * fc;
        __nv_bfloat16 qh = __float2bfloat16(xq);
        float rq = xq - __bfloat162float(qh);
        __nv_bfloat16 qm = __float2bfloat16(rq);
        __nv_bfloat16 ql = __float2bfloat16(rq - __bfloat162float(qm));
        size_t oq = ((size_t)(b*HH + h)*SS + s)*DH + i;
        g_Qh[oq] = qh; g_Qm[oq] = qm; g_Ql[oq] = ql;
        qsm[i*65 + sl] = xq;
        ksm[i*65 + sl] = k[gin] * fc;
    }
    __syncthreads();
    for (int idx = tid; idx < 64*64; idx += 256) {
        int i = idx >> 6, sl = idx & 63;
        float xk = ksm[i*65 + sl];
        __nv_bfloat16 kh = __float2bfloat16(xk);
        float rk = xk - __bfloat162float(kh);
        __nv_bfloat16 km = __float2bfloat16(rk);
        __nv_bfloat16 kl = __float2bfloat16(rk - __bfloat162float(km));
        size_t ok = ((size_t)(b*HH + h)*DH + i)*SS + st*64 + sl;
        g_Kh[ok] = kh; g_Km[ok] = km; g_Kl[ok] = kl;
    }
    // norms
    if (tid < 64) {
        float sq = 0.0f, sk = 0.0f;
        #pragma unroll 8
        for (int i = 0; i < 64; i++) {
            float a = qsm[i*65 + tid]; sq = fmaf(a, a, sq);
            float c = ksm[i*65 + tid]; sk = fmaf(c, c, sk);
        }
        g_Qn[(size_t)(b*HH + h)*SS + st*64 + tid] = sqrtf(sq);
        kcol[tid] = sqrtf(sk);
    }
    __syncthreads();
    if (tid == 0) {
        float m = 0.0f;
        for (int i = 0; i < 64; i++) m = fmaxf(m, kcol[i]);
        g_Kn[(size_t)(b*HH + h)*NT + st] = m;
    }
}

__global__ void prep_v(const float* __restrict__ v) {
    const int st = blockIdx.x, h = blockIdx.y, b = blockIdx.z;
    const int tid = threadIdx.x;
    for (int idx = tid; idx < 64*32; idx += 256) {
        int s = idx >> 5, d4 = idx & 31;
        float4 x = *(const float4*)&v[((size_t)(b*SS + st*64 + s)*HH + h)*DD + d4*4];
        __nv_bfloat16 h0 = __float2bfloat16(x.x), h1 = __float2bfloat16(x.y);
        __nv_bfloat16 h2 = __float2bfloat16(x.z), h3 = __float2bfloat16(x.w);
        __nv_bfloat16 l0 = __float2bfloat16(x.x - __bfloat162float(h0));
        __nv_bfloat16 l1 = __float2bfloat16(x.y - __bfloat162float(h1));
        __nv_bfloat16 l2 = __float2bfloat16(x.z - __bfloat162float(h2));
        __nv_bfloat16 l3 = __float2bfloat16(x.w - __bfloat162float(h3));
        size_t o = ((size_t)(b*HH + h)*SS + st*64 + s)*DD + d4*4;
        __nv_bfloat162* ph = (__nv_bfloat162*)(g_Vhi + o);
        __nv_bfloat162* pl = (__nv_bfloat162*)(g_Vlo + o);
        __nv_bfloat162 a; a.x = h0; a.y = h1; ph[0] = a;
        a.x = h2; a.y = h3; ph[1] = a;
        a.x = l0; a.y = l1; pl[0] = a;
        a.x = l2; a.y = l3; pl[1] = a;
    }
}

// ---------------- tile fills ----------------
__device__ __forceinline__ void fill_K(uint32_t sb, int buf, int kt, int tid,
                                       const __nv_bfloat16* Kh, const __nv_bfloat16* Km,
                                       const __nv_bfloat16* Kl) {
    uint32_t kd = sb + OFF_K + (uint32_t)buf*KBUF;
    #pragma unroll
    for (int it = 0; it < 2; it++) {
        int idx = tid + it*NTHR;
        int row = idx >> 3, cc = idx & 7;
        size_t so = (size_t)row*SS + kt*BN + cc*8;
        uint32_t d = kd + (uint32_t)row*KROWB + cc*16;
        cp_async16(d, Kh + so);
        cp_async16(d + KSPL, Km + so);
        cp_async16(d + 2*KSPL, Kl + so);
    }
}
__device__ __forceinline__ void fill_V(uint32_t sb, int buf, int kt, int tid,
                                       const __nv_bfloat16* Vh, const __nv_bfloat16* Vl) {
    uint32_t vd = sb + OFF_V + (uint32_t)buf*VBUF;
    #pragma unroll
    for (int it = 0; it < 4; it++) {
        int idx = tid + it*NTHR;
        int row = idx >> 4, cc = idx & 15;
        size_t so = (size_t)(kt*BN + row)*DD + cc*8;
        uint32_t d = vd + (uint32_t)row*VROWB + cc*16;
        cp_async16(d, Vh + so);
        cp_async16(d + VSPL, Vl + so);
    }
}

// ---------------- flash attention: reverse order + CS-bound GEMM1 skip ----------------
// 8 warps; warp w owns rows w*16..+15 end-to-end. Key tiles processed s2 high -> low.
// Before GEMM1, a rigorous Cauchy-Schwarz bound ||q'||*||K't|| proves tile deadness:
// if bound*sc2 <= mrow-40 for all 16 rows, GEMM1+softmax+GEMM2 are all skipped
// (skipped weights < 2^-40 of running l -> identical result).
__global__ __launch_bounds__(NTHR, 1)
void attn_kernel(float* __restrict__ out) {
    extern __shared__ char smem[];
    const uint32_t sbase = (uint32_t)__cvta_generic_to_shared(smem);
    float* knsm = (float*)(smem + OFF_KN);

    const int qt = blockIdx.x, h = blockIdx.y, b = blockIdx.z;
    const int tid = threadIdx.x;
    const int wid = tid >> 5, lane = tid & 31;

    const __nv_bfloat16* Qh_g = g_Qh + ((size_t)(b*HH + h)*SS + qt*BM)*DH;
    const __nv_bfloat16* Qm_g = g_Qm + ((size_t)(b*HH + h)*SS + qt*BM)*DH;
    const __nv_bfloat16* Ql_g = g_Ql + ((size_t)(b*HH + h)*SS + qt*BM)*DH;
    const __nv_bfloat16* Kh_g = g_Kh + (size_t)(b*HH + h)*DH*SS;
    const __nv_bfloat16* Km_g = g_Km + (size_t)(b*HH + h)*DH*SS;
    const __nv_bfloat16* Kl_g = g_Kl + (size_t)(b*HH + h)*DH*SS;
    const __nv_bfloat16* Vh_g = g_Vhi + (size_t)(b*HH + h)*SS*DD;
    const __nv_bfloat16* Vl_g = g_Vlo + (size_t)(b*HH + h)*SS*DD;

    // ---- prologue: Q (3 splits) + tiles NT-1, NT-2; Kn table ----
    {
        const __nv_bfloat16* qs[3] = {Qh_g, Qm_g, Ql_g};
        #pragma unroll
        for (int sp = 0; sp < 3; sp++)
            #pragma unroll
            for (int it = 0; it < 4; it++) {
                int idx = tid + it*NTHR;
                int row = idx >> 3, cc = idx & 7;
                cp_async16(sbase + OFF_QH + (uint32_t)sp*QSPL + (uint32_t)row*QROWB + cc*16,
                           qs[sp] + (size_t)row*DH + cc*8);
            }
    }
    if (tid < NT) knsm[tid] = g_Kn[(size_t)(b*HH + h)*NT + tid];
    fill_K(sbase, (NT-1) & 1, NT-1, tid, Kh_g, Km_g, Kl_g);
    fill_V(sbase, (NT-1) & 1, NT-1, tid, Vh_g, Vl_g);
    cp_commit();
    fill_K(sbase, (NT-2) & 1, NT-2, tid, Kh_g, Km_g, Kl_g);
    fill_V(sbase, (NT-2) & 1, NT-2, tid, Vh_g, Vl_g);
    cp_commit();
    cp_wait_1();                       // tile NT-1 resident
    __syncthreads();

    // ---- Q fragments: load once, keep in registers ----
    uint32_t qh[4][4], qm[4][4], ql[4][4];
    {
        uint32_t qf = sbase + OFF_QH + (uint32_t)(wid*16 + (lane & 15))*QROWB
                    + ((lane >> 4) << 4);
        #pragma unroll
        for (int ks = 0; ks < 4; ks++) {
            ldmx4(qh[ks], qf + ks*32);
            ldmx4(qm[ks], qf + QSPL + ks*32);
            ldmx4(ql[ks], qf + 2*QSPL + ks*32);
        }
    }

    const float sc2 = 1.44269504088896340736f / 64.0f;  // log2(e)/64
    // per-lane row norms (rows r0 = wid*16+(lane>>2), r1 = r0+8)
    const float qn0 = g_Qn[(size_t)(b*HH + h)*SS + qt*BM + wid*16 + (lane >> 2)];
    const float qn1 = g_Qn[(size_t)(b*HH + h)*SS + qt*BM + wid*16 + (lane >> 2) + 8];

    float mrow0 = -INFINITY, mrow1 = -INFINITY, lrow0 = 0.0f, lrow1 = 0.0f;
    float c[16][4];
    #pragma unroll
    for (int t = 0; t < 16; t++)
        #pragma unroll
        for (int j = 0; j < 4; j++) c[t][j] = 0.0f;

    const uint32_t kfb = sbase + OFF_K + (uint32_t)(lane & 15)*KROWB + ((lane >> 4) << 4);
    const uint32_t vfb = sbase + OFF_V + (uint32_t)(lane & 15)*VROWB + ((lane >> 4) << 4);

    for (int kt = NT - 1; kt >= 0; --kt) {
        const int buf = kt & 1;

        // ---- Cauchy-Schwarz pre-bound: can this tile matter for any of my rows? ----
        const float kn = knsm[kt];
        bool blive = (qn0*kn*sc2 > mrow0 - 40.0f) || (qn1*kn*sc2 > mrow1 - 40.0f);
        if (__any_sync(0xffffffffu, blive)) {
            const uint32_t kb = kfb + (uint32_t)buf*KBUF;
            const uint32_t vb = vfb + (uint32_t)buf*VBUF;

            // ---- GEMM1 (tensor): S = Q'K'^T via tri-split bf16, 6 terms ----
            float s[8][4];
            #pragma unroll
            for (int t = 0; t < 8; t++)
                #pragma unroll
                for (int j = 0; j < 4; j++) s[t][j] = 0.0f;

            #pragma unroll
            for (int ks = 0; ks < 4; ks++) {
                #pragma unroll
                for (int nb = 0; nb < 4; nb++) {
                    uint32_t ka = kb + (uint32_t)(ks*16)*KROWB + nb*32;
                    uint32_t kh4[4], km4[4], kl4[4];
                    ldmx4t(kh4, ka);
                    ldmx4t(km4, ka + KSPL);
                    ldmx4t(kl4, ka + 2*KSPL);
                    float* s0 = s[2*nb];
                    float* s1 = s[2*nb + 1];
                    mma2(s0, qh[ks], kh4[0], kh4[1]); mma2(s1, qh[ks], kh4[2], kh4[3]);
                    mma2(s0, qh[ks], km4[0], km4[1]); mma2(s1, qh[ks], km4[2], km4[3]);
                    mma2(s0, qm[ks], kh4[0], kh4[1]); mma2(s1, qm[ks], kh4[2], kh4[3]);
                    mma2(s0, qh[ks], kl4[0], kl4[1]); mma2(s1, qh[ks], kl4[2], kl4[3]);
                    mma2(s0, ql[ks], kh4[0], kh4[1]); mma2(s1, ql[ks], kh4[2], kh4[3]);
                    mma2(s0, qm[ks], km4[0], km4[1]); mma2(s1, qm[ks], km4[2], km4[3]);
                }
            }

            // ---- row max + exact liveness vote ----
            float mx0 = -INFINITY, mx1 = -INFINITY;
            #pragma unroll
            for (int t = 0; t < 8; t++) {
                mx0 = fmaxf(mx0, fmaxf(s[t][0], s[t][1]));
                mx1 = fmaxf(mx1, fmaxf(s[t][2], s[t][3]));
            }
            mx0 = fmaxf(mx0, __shfl_xor_sync(0xffffffffu, mx0, 1));
            mx0 = fmaxf(mx0, __shfl_xor_sync(0xffffffffu, mx0, 2));
            mx1 = fmaxf(mx1, __shfl_xor_sync(0xffffffffu, mx1, 1));
            mx1 = fmaxf(mx1, __shfl_xor_sync(0xffffffffu, mx1, 2));

            bool livelane = (mx0*sc2 > mrow0 - 40.0f) || (mx1*sc2 > mrow1 - 40.0f);
            if (__any_sync(0xffffffffu, livelane)) {
                float mn0 = fmaxf(mrow0, mx0*sc2);
                float mn1 = fmaxf(mrow1, mx1*sc2);
                float f0 = exp2f(mrow0 - mn0);   // 0 on first tile
                float f1 = exp2f(mrow1 - mn1);
                mrow0 = mn0; mrow1 = mn1;

                uint32_t ph[4][4], pl[4][4];
                float sum0 = 0.0f, sum1 = 0.0f;
                #pragma unroll
                for (int t = 0; t < 8; t++) {
                    float p0 = exp2f(fmaf(s[t][0], sc2, -mn0));
                    float p1 = exp2f(fmaf(s[t][1], sc2, -mn0));
                    float p2 = exp2f(fmaf(s[t][2], sc2, -mn1));
                    float p3 = exp2f(fmaf(s[t][3], sc2, -mn1));
                    sum0 += p0 + p1; sum1 += p2 + p3;
                    float h0 = __bfloat162float(__float2bfloat16(p0));
                    float h1 = __bfloat162float(__float2bfloat16(p1));
                    float h2 = __bfloat162float(__float2bfloat16(p2));
                    float h3 = __bfloat162float(__float2bfloat16(p3));
                    int ks = t >> 1, off = (t & 1)*2;
                    ph[ks][off]     = pk2(h0, h1);
                    ph[ks][off + 1] = pk2(h2, h3);
                    pl[ks][off]     = pk2(p0 - h0, p1 - h1);
                    pl[ks][off + 1] = pk2(p2 - h2, p3 - h3);
                }
                sum0 += __shfl_xor_sync(0xffffffffu, sum0, 1);
                sum0 += __shfl_xor_sync(0xffffffffu, sum0, 2);
                sum1 += __shfl_xor_sync(0xffffffffu, sum1, 1);
                sum1 += __shfl_xor_sync(0xffffffffu, sum1, 2);
                lrow0 = lrow0*f0 + sum0;
                lrow1 = lrow1*f1 + sum1;

                // rescale running O
                #pragma unroll
                for (int t = 0; t < 16; t++) {
                    c[t][0] *= f0; c[t][1] *= f0;
                    c[t][2] *= f1; c[t][3] *= f1;
                }

                // ---- GEMM2 (tensor): O += Ph*Vh + Ph*Vl + Pl*Vh ----
                #pragma unroll
                for (int ks = 0; ks < 4; ks++) {
                    #pragma unroll
                    for (int db = 0; db < 8; db++) {
                        uint32_t va = vb + (uint32_t)(ks*16)*VROWB + db*32;
                        uint32_t vh4[4], vl4[4];
                        ldmx4t(vh4, va);
                        ldmx4t(vl4, va + VSPL);
                        float* c0 = c[2*db];
                        float* c1 = c[2*db + 1];
                        mma2(c0, ph[ks], vh4[0], vh4[1]); mma2(c1, ph[ks], vh4[2], vh4[3]);
                        mma2(c0, ph[ks], vl4[0], vl4[1]); mma2(c1, ph[ks], vl4[2], vl4[3]);
                        mma2(c0, pl[ks], vh4[0], vh4[1]); mma2(c1, pl[ks], vh4[2], vh4[3]);
                    }
                }
            }
        }

        if (kt == 0) break;
        __syncthreads();                      // all warps done with buf kt&1
        if (kt - 2 >= 0) {
            fill_K(sbase, buf, kt - 2, tid, Kh_g, Km_g, Kl_g);
            fill_V(sbase, buf, kt - 2, tid, Vh_g, Vl_g);
        }
        cp_commit();
        cp_wait_1();                          // tile kt-1 resident
        __syncthreads();                      // visible to all warps
    }

    // ---- epilogue: normalize + store ----
    {
        float il0 = 1.0f / lrow0;
        float il1 = 1.0f / lrow1;
        int r0 = qt*BM + wid*16 + (lane >> 2);
        float* op0 = out + (((size_t)b*SS + r0)*HH + h)*DD + (lane & 3)*2;
        float* op1 = op0 + (size_t)8*HH*DD;   // row+8 -> s+8
        #pragma unroll
        for (int t = 0; t < 16; t++) {
            *(float2*)(op0 + t*8) = make_float2(c[t][0]*il0, c[t][1]*il0);
            *(float2*)(op1 + t*8) = make_float2(c[t][2]*il1, c[t][3]*il1);
        }
    }
}

extern "C" void kernel_launch(void* const* d_in, const int* in_sizes, int n_in,
                              void* d_out, int out_size) {
    const float* q = (const float*)d_in[0];
    const float* k = (const float*)d_in[1];
    const float* v = (const float*)d_in[2];
    float* out = (float*)d_out;

    cudaFuncSetAttribute(attn_kernel, cudaFuncAttributeMaxDynamicSharedMemorySize, SMEM_TOTAL);

    init_inv<<<1, 64>>>();
    dim3 pgrid(SS/64, HH, BB);
    prep_qk<<<pgrid, 256>>>(q, k);
    prep_v<<<pgrid, 256>>>(v);

    dim3 grid(SS/BM, HH, BB);
    attn_kernel<<<grid, NTHR, SMEM_TOTAL>>>(out);
}